// round 8
// baseline (speedup 1.0000x reference)
#include <cuda_runtime.h>
#include <cuda_fp16.h>
#include <cstdint>

#define M_DIM 4096
#define N_DIM 8192
#define K_DIM 2048

#define BM 128
#define BN 128
#define BK 64
#define NIT (K_DIM / BK)      // 32
#define NSTAGE 3
#define ROW_HALVES 64
#define A_HALVES (BM * ROW_HALVES)          // 8192
#define B_HALVES (BN * ROW_HALVES)          // 8192
#define STAGE_HALVES (A_HALVES + B_HALVES)  // 16384 (32 KB)
#define SMEM_BYTES (NSTAGE * STAGE_HALVES * 2)  // 98304 -> 2 CTAs/SM

// Static scratch (allocation-free rule): fp16 weights + fp16 activations
__device__ __align__(16) __half g_w[(size_t)N_DIM * K_DIM];  // 32 MB
__device__ __align__(16) __half g_x[(size_t)M_DIM * K_DIM];  // 16 MB

__constant__ float c_lut[16] = {
    -1.0f, -0.5f, -0.333333f, -0.2f, -0.142857f, -0.090909f, -0.076923f,
    0.0f, 0.076923f, 0.090909f, 0.142857f, 0.2f, 0.333333f, 0.5f, 1.0f, 0.0f};

// ---------------------------------------------------------------------------
// Fused prologue: blocks [0,8192) dequant w (smem LUT), [8192,12288) convert x
// ---------------------------------------------------------------------------
#define W_BLOCKS (N_DIM * (K_DIM / 8) / 256)   // 8192
#define X_BLOCKS (M_DIM * (K_DIM / 8) / 256)   // 4096
__global__ __launch_bounds__(256) void prep_kernel(const float* __restrict__ x,
                                                   const int* __restrict__ gi,
                                                   const float* __restrict__ scale_p) {
    int b = blockIdx.x;
    if (b < W_BLOCKS) {
        __shared__ float lut[16];
        if (threadIdx.x < 16) lut[threadIdx.x] = c_lut[threadIdx.x] * (*scale_p);
        __syncthreads();
        size_t t = (size_t)b * blockDim.x + threadIdx.x;
        const int4* gp = reinterpret_cast<const int4*>(gi) + t * 2;
        int4 a = gp[0];
        int4 c = gp[1];
        __half2 h0 = __floats2half2_rn(lut[a.x], lut[a.y]);
        __half2 h1 = __floats2half2_rn(lut[a.z], lut[a.w]);
        __half2 h2 = __floats2half2_rn(lut[c.x], lut[c.y]);
        __half2 h3 = __floats2half2_rn(lut[c.z], lut[c.w]);
        uint4 o;
        o.x = *reinterpret_cast<uint32_t*>(&h0);
        o.y = *reinterpret_cast<uint32_t*>(&h1);
        o.z = *reinterpret_cast<uint32_t*>(&h2);
        o.w = *reinterpret_cast<uint32_t*>(&h3);
        *reinterpret_cast<uint4*>(g_w + t * 8) = o;
    } else {
        size_t t = (size_t)(b - W_BLOCKS) * blockDim.x + threadIdx.x;
        const float4* xp = reinterpret_cast<const float4*>(x) + t * 2;
        float4 a = xp[0];
        float4 c = xp[1];
        __half2 h0 = __floats2half2_rn(a.x, a.y);
        __half2 h1 = __floats2half2_rn(a.z, a.w);
        __half2 h2 = __floats2half2_rn(c.x, c.y);
        __half2 h3 = __floats2half2_rn(c.z, c.w);
        uint4 o;
        o.x = *reinterpret_cast<uint32_t*>(&h0);
        o.y = *reinterpret_cast<uint32_t*>(&h1);
        o.z = *reinterpret_cast<uint32_t*>(&h2);
        o.w = *reinterpret_cast<uint32_t*>(&h3);
        *reinterpret_cast<uint4*>(g_x + t * 8) = o;
    }
}

// ---------------------------------------------------------------------------
// helpers
// ---------------------------------------------------------------------------
__device__ __forceinline__ void cp16(__half* dst, const __half* src) {
    uint32_t d = (uint32_t)__cvta_generic_to_shared(dst);
    asm volatile("cp.async.cg.shared.global [%0], [%1], 16;\n" :: "r"(d), "l"(src));
}

__device__ __forceinline__ void ldsm4(uint32_t* r, const __half* p) {
    uint32_t a = (uint32_t)__cvta_generic_to_shared(p);
    asm volatile("ldmatrix.sync.aligned.m8n8.x4.shared.b16 {%0,%1,%2,%3}, [%4];\n"
                 : "=r"(r[0]), "=r"(r[1]), "=r"(r[2]), "=r"(r[3]) : "r"(a));
}

// fp16-accumulate mma (2x rate vs f32-acc on legacy path)
__device__ __forceinline__ void mma16816_h(uint32_t* c, const uint32_t* a, const uint32_t* b) {
    asm volatile(
        "mma.sync.aligned.m16n8k16.row.col.f16.f16.f16.f16 "
        "{%0,%1}, {%2,%3,%4,%5}, {%6,%7}, {%0,%1};\n"
        : "+r"(c[0]), "+r"(c[1])
        : "r"(a[0]), "r"(a[1]), "r"(a[2]), "r"(a[3]), "r"(b[0]), "r"(b[1]));
}

// swizzled address: row (128B rows), 16B-chunk index. phys chunk = chunk ^ (row & 7)
__device__ __forceinline__ const __half* swz(const __half* base, int row, int chunk) {
    return base + row * ROW_HALVES + ((chunk ^ (row & 7)) << 3);
}
__device__ __forceinline__ __half* swzw(__half* base, int row, int chunk) {
    return base + row * ROW_HALVES + ((chunk ^ (row & 7)) << 3);
}

// ---------------------------------------------------------------------------
// GEMM: out[M,N] = g_x[M,K] @ g_w[N,K]^T
// CTA 128x128x64, 8 warps (4M x 2N), warp tile 32x64, 3-stage cp.async,
// XOR swizzle, 2 CTAs/SM. Hybrid accumulation: fp16 mma accumulators,
// promoted to fp32 every 2 k-steps (K=32 chunks).
// ---------------------------------------------------------------------------
__global__ __launch_bounds__(256, 2) void gemm_kernel(float* __restrict__ out) {
    extern __shared__ __half sm[];

    const int tid = threadIdx.x;
    const int warp = tid >> 5;
    const int lane = tid & 31;
    const int wm = warp & 3;   // 0..3 : 32-row slice
    const int wn = warp >> 2;  // 0..1 : 64-col slice
    const int m0 = blockIdx.y * BM;
    const int n0 = blockIdx.x * BN;

    const int crow = tid >> 1;           // 0..127
    const int cchk = (tid & 1) * 4;      // chunks 0-3 or 4-7

    float acc[2][8][4];
    uint32_t acch[2][8][2];
#pragma unroll
    for (int i = 0; i < 2; i++)
#pragma unroll
        for (int j = 0; j < 8; j++) {
#pragma unroll
            for (int k = 0; k < 4; k++) acc[i][j][k] = 0.0f;
            acch[i][j][0] = 0u; acch[i][j][1] = 0u;
        }

    auto load_stage = [&](int s, int k0) {
        __half* a = sm + s * STAGE_HALVES;
        __half* b = a + A_HALVES;
        const __half* ga = g_x + (size_t)(m0 + crow) * K_DIM + k0 + cchk * 8;
        const __half* gb = g_w + (size_t)(n0 + crow) * K_DIM + k0 + cchk * 8;
#pragma unroll
        for (int j = 0; j < 4; j++) {
            cp16(swzw(a, crow, cchk + j), ga + j * 8);
            cp16(swzw(b, crow, cchk + j), gb + j * 8);
        }
        asm volatile("cp.async.commit_group;\n");
    };

    load_stage(0, 0);
    load_stage(1, BK);

    for (int it = 0; it < NIT; ++it) {
        asm volatile("cp.async.wait_group 1;\n");
        __syncthreads();

        if (it + 2 < NIT) load_stage((it + 2) % NSTAGE, (it + 2) * BK);

        const __half* a_s = sm + (it % NSTAGE) * STAGE_HALVES;
        const __half* b_s = a_s + A_HALVES;

#pragma unroll
        for (int ks = 0; ks < 4; ks++) {
            const int kc = ks * 2;
            uint32_t af[2][4];
#pragma unroll
            for (int mt = 0; mt < 2; mt++)
                ldsm4(af[mt], swz(a_s, wm * 32 + mt * 16 + (lane & 15), kc + (lane >> 4)));
            uint32_t bf[8][2];
#pragma unroll
            for (int np = 0; np < 4; np++) {
                uint32_t r[4];
                ldsm4(r, swz(b_s, wn * 64 + np * 16 + (lane & 7) + ((lane >> 4) & 1) * 8,
                             kc + ((lane >> 3) & 1)));
                bf[np * 2][0] = r[0]; bf[np * 2][1] = r[1];
                bf[np * 2 + 1][0] = r[2]; bf[np * 2 + 1][1] = r[3];
            }
#pragma unroll
            for (int mt = 0; mt < 2; mt++)
#pragma unroll
                for (int nt = 0; nt < 8; nt++)
                    mma16816_h(acch[mt][nt], af[mt], bf[nt]);

            if (ks & 1) {
                // promote fp16 partials (K=32 chunk) into fp32 accumulators
#pragma unroll
                for (int mt = 0; mt < 2; mt++)
#pragma unroll
                    for (int nt = 0; nt < 8; nt++) {
                        float2 f0 = __half22float2(*reinterpret_cast<__half2*>(&acch[mt][nt][0]));
                        float2 f1 = __half22float2(*reinterpret_cast<__half2*>(&acch[mt][nt][1]));
                        acc[mt][nt][0] += f0.x; acc[mt][nt][1] += f0.y;
                        acc[mt][nt][2] += f1.x; acc[mt][nt][3] += f1.y;
                        acch[mt][nt][0] = 0u; acch[mt][nt][1] = 0u;
                    }
            }
        }
    }

    // epilogue: direct fp32 stores
#pragma unroll
    for (int mt = 0; mt < 2; mt++) {
#pragma unroll
        for (int nt = 0; nt < 8; nt++) {
            int row = m0 + wm * 32 + mt * 16 + (lane >> 2);
            int col = n0 + wn * 64 + nt * 8 + (lane & 3) * 2;
            float2 v0 = make_float2(acc[mt][nt][0], acc[mt][nt][1]);
            float2 v1 = make_float2(acc[mt][nt][2], acc[mt][nt][3]);
            *reinterpret_cast<float2*>(out + (size_t)row * N_DIM + col) = v0;
            *reinterpret_cast<float2*>(out + (size_t)(row + 8) * N_DIM + col) = v1;
        }
    }
}

// ---------------------------------------------------------------------------
// kernel_launch
// ---------------------------------------------------------------------------
extern "C" void kernel_launch(void* const* d_in, const int* in_sizes, int n_in,
                              void* d_out, int out_size) {
    const float* x = (const float*)d_in[0];
    const int* gi = (const int*)d_in[1];
    const float* scale = (const float*)d_in[2];
    float* out = (float*)d_out;

    prep_kernel<<<W_BLOCKS + X_BLOCKS, 256>>>(x, gi, scale);

    cudaFuncSetAttribute(gemm_kernel, cudaFuncAttributeMaxDynamicSharedMemorySize, SMEM_BYTES);
    dim3 grid(N_DIM / BN, M_DIM / BM);  // (64, 32)
    gemm_kernel<<<grid, 256, SMEM_BYTES>>>(out);
}

// round 9
// speedup vs baseline: 1.3002x; 1.3002x over previous
#include <cuda_runtime.h>
#include <cuda_fp16.h>
#include <cstdint>

#define M_DIM 4096
#define N_DIM 8192
#define K_DIM 2048

#define BM 128
#define BN 128
#define BK 64
#define NIT (K_DIM / BK)      // 32
#define NSTAGE 3
#define ROW_HALVES 64
#define A_HALVES (BM * ROW_HALVES)          // 8192
#define B_HALVES (BN * ROW_HALVES)          // 8192
#define STAGE_HALVES (A_HALVES + B_HALVES)  // 16384 (32 KB)
#define SMEM_BYTES (NSTAGE * STAGE_HALVES * 2)  // 98304 -> 2 CTAs/SM

// Static scratch (allocation-free rule): fp16 weights + fp16 activations
__device__ __align__(16) __half g_w[(size_t)N_DIM * K_DIM];  // 32 MB
__device__ __align__(16) __half g_x[(size_t)M_DIM * K_DIM];  // 16 MB

__constant__ float c_lut[16] = {
    -1.0f, -0.5f, -0.333333f, -0.2f, -0.142857f, -0.090909f, -0.076923f,
    0.0f, 0.076923f, 0.090909f, 0.142857f, 0.2f, 0.333333f, 0.5f, 1.0f, 0.0f};

// ---------------------------------------------------------------------------
// Fused prologue: blocks [0,8192) dequant w (smem LUT), [8192,12288) convert x
// ---------------------------------------------------------------------------
#define W_BLOCKS (N_DIM * (K_DIM / 8) / 256)   // 8192
#define X_BLOCKS (M_DIM * (K_DIM / 8) / 256)   // 4096
__global__ __launch_bounds__(256) void prep_kernel(const float* __restrict__ x,
                                                   const int* __restrict__ gi,
                                                   const float* __restrict__ scale_p) {
    int b = blockIdx.x;
    if (b < W_BLOCKS) {
        __shared__ float lut[16];
        if (threadIdx.x < 16) lut[threadIdx.x] = c_lut[threadIdx.x] * (*scale_p);
        __syncthreads();
        size_t t = (size_t)b * blockDim.x + threadIdx.x;
        const int4* gp = reinterpret_cast<const int4*>(gi) + t * 2;
        int4 a = gp[0];
        int4 c = gp[1];
        __half2 h0 = __floats2half2_rn(lut[a.x], lut[a.y]);
        __half2 h1 = __floats2half2_rn(lut[a.z], lut[a.w]);
        __half2 h2 = __floats2half2_rn(lut[c.x], lut[c.y]);
        __half2 h3 = __floats2half2_rn(lut[c.z], lut[c.w]);
        uint4 o;
        o.x = *reinterpret_cast<uint32_t*>(&h0);
        o.y = *reinterpret_cast<uint32_t*>(&h1);
        o.z = *reinterpret_cast<uint32_t*>(&h2);
        o.w = *reinterpret_cast<uint32_t*>(&h3);
        *reinterpret_cast<uint4*>(g_w + t * 8) = o;
    } else {
        size_t t = (size_t)(b - W_BLOCKS) * blockDim.x + threadIdx.x;
        const float4* xp = reinterpret_cast<const float4*>(x) + t * 2;
        float4 a = xp[0];
        float4 c = xp[1];
        __half2 h0 = __floats2half2_rn(a.x, a.y);
        __half2 h1 = __floats2half2_rn(a.z, a.w);
        __half2 h2 = __floats2half2_rn(c.x, c.y);
        __half2 h3 = __floats2half2_rn(c.z, c.w);
        uint4 o;
        o.x = *reinterpret_cast<uint32_t*>(&h0);
        o.y = *reinterpret_cast<uint32_t*>(&h1);
        o.z = *reinterpret_cast<uint32_t*>(&h2);
        o.w = *reinterpret_cast<uint32_t*>(&h3);
        *reinterpret_cast<uint4*>(g_x + t * 8) = o;
    }
}

// ---------------------------------------------------------------------------
// helpers
// ---------------------------------------------------------------------------
__device__ __forceinline__ void cp16(__half* dst, const __half* src) {
    uint32_t d = (uint32_t)__cvta_generic_to_shared(dst);
    asm volatile("cp.async.cg.shared.global [%0], [%1], 16;\n" :: "r"(d), "l"(src));
}

__device__ __forceinline__ void ldsm4(uint32_t* r, const __half* p) {
    uint32_t a = (uint32_t)__cvta_generic_to_shared(p);
    asm volatile("ldmatrix.sync.aligned.m8n8.x4.shared.b16 {%0,%1,%2,%3}, [%4];\n"
                 : "=r"(r[0]), "=r"(r[1]), "=r"(r[2]), "=r"(r[3]) : "r"(a));
}

__device__ __forceinline__ void mma16816(float* c, const uint32_t* a, const uint32_t* b) {
    asm volatile(
        "mma.sync.aligned.m16n8k16.row.col.f32.f16.f16.f32 "
        "{%0,%1,%2,%3}, {%4,%5,%6,%7}, {%8,%9}, {%0,%1,%2,%3};\n"
        : "+f"(c[0]), "+f"(c[1]), "+f"(c[2]), "+f"(c[3])
        : "r"(a[0]), "r"(a[1]), "r"(a[2]), "r"(a[3]), "r"(b[0]), "r"(b[1]));
}

// swizzled address: row (128B rows), 16B-chunk index. phys chunk = chunk ^ (row & 7)
__device__ __forceinline__ const __half* swz(const __half* base, int row, int chunk) {
    return base + row * ROW_HALVES + ((chunk ^ (row & 7)) << 3);
}
__device__ __forceinline__ __half* swzw(__half* base, int row, int chunk) {
    return base + row * ROW_HALVES + ((chunk ^ (row & 7)) << 3);
}

// ---------------------------------------------------------------------------
// GEMM: out[M,N] = g_x[M,K] @ g_w[N,K]^T
// CTA 128x128x64, 8 warps (4M x 2N), warp tile 32x64, 3-stage cp.async,
// XOR swizzle, 2 CTAs/SM, fp32 accumulators.
// Intra-iter fragment double-buffering: k-step ks+1 LDSMs issue before
// ks's MMAs so the post-barrier LDSM burst is 6 (not 24) and ldsm latency
// hides under MMA issue.
// ---------------------------------------------------------------------------
__global__ __launch_bounds__(256, 2) void gemm_kernel(float* __restrict__ out) {
    extern __shared__ __half sm[];

    const int tid = threadIdx.x;
    const int warp = tid >> 5;
    const int lane = tid & 31;
    const int wm = warp & 3;   // 0..3 : 32-row slice
    const int wn = warp >> 2;  // 0..1 : 64-col slice
    const int m0 = blockIdx.y * BM;
    const int n0 = blockIdx.x * BN;

    const int crow = tid >> 1;           // 0..127
    const int cchk = (tid & 1) * 4;      // chunks 0-3 or 4-7

    // fragment row/chunk coordinates (fixed per thread)
    const int arow0 = wm * 32 + (lane & 15);
    const int achk = lane >> 4;                                   // 0..1
    const int brow = wn * 64 + (lane & 7) + ((lane >> 4) & 1) * 8;
    const int bchk = (lane >> 3) & 1;                             // 0..1

    float acc[2][8][4];
#pragma unroll
    for (int i = 0; i < 2; i++)
#pragma unroll
        for (int j = 0; j < 8; j++)
#pragma unroll
            for (int k = 0; k < 4; k++) acc[i][j][k] = 0.0f;

    auto load_stage = [&](int s, int k0) {
        __half* a = sm + s * STAGE_HALVES;
        __half* b = a + A_HALVES;
        const __half* ga = g_x + (size_t)(m0 + crow) * K_DIM + k0 + cchk * 8;
        const __half* gb = g_w + (size_t)(n0 + crow) * K_DIM + k0 + cchk * 8;
#pragma unroll
        for (int j = 0; j < 4; j++) {
            cp16(swzw(a, crow, cchk + j), ga + j * 8);
            cp16(swzw(b, crow, cchk + j), gb + j * 8);
        }
        asm volatile("cp.async.commit_group;\n");
    };

    load_stage(0, 0);
    load_stage(1, BK);

    uint32_t af0[2][4], af1[2][4];
    uint32_t bf0[8][2], bf1[8][2];

    // fragment loaders for a given 16-col k-step base chunk kc
#define LOAD_FRAGS(AF, BF, a_s, b_s, kc)                                         \
    do {                                                                         \
        _Pragma("unroll")                                                        \
        for (int mt = 0; mt < 2; mt++)                                           \
            ldsm4(AF[mt], swz(a_s, arow0 + mt * 16, (kc) + achk));               \
        _Pragma("unroll")                                                        \
        for (int np = 0; np < 4; np++) {                                         \
            uint32_t r_[4];                                                      \
            ldsm4(r_, swz(b_s, brow + np * 16, (kc) + bchk));                    \
            BF[np * 2][0] = r_[0]; BF[np * 2][1] = r_[1];                        \
            BF[np * 2 + 1][0] = r_[2]; BF[np * 2 + 1][1] = r_[3];                \
        }                                                                        \
    } while (0)

#define MMA_STEP(AF, BF)                                                         \
    do {                                                                         \
        _Pragma("unroll")                                                        \
        for (int mt = 0; mt < 2; mt++)                                           \
            _Pragma("unroll")                                                    \
            for (int nt = 0; nt < 8; nt++)                                       \
                mma16816(acc[mt][nt], AF[mt], BF[nt]);                           \
    } while (0)

    for (int it = 0; it < NIT; ++it) {
        asm volatile("cp.async.wait_group 1;\n");
        __syncthreads();

        if (it + 2 < NIT) load_stage((it + 2) % NSTAGE, (it + 2) * BK);

        const __half* a_s = sm + (it % NSTAGE) * STAGE_HALVES;
        const __half* b_s = a_s + A_HALVES;

        LOAD_FRAGS(af0, bf0, a_s, b_s, 0);        // k-step 0
        LOAD_FRAGS(af1, bf1, a_s, b_s, 2);        // prefetch k-step 1
        MMA_STEP(af0, bf0);
        LOAD_FRAGS(af0, bf0, a_s, b_s, 4);        // prefetch k-step 2
        MMA_STEP(af1, bf1);
        LOAD_FRAGS(af1, bf1, a_s, b_s, 6);        // prefetch k-step 3
        MMA_STEP(af0, bf0);
        MMA_STEP(af1, bf1);
    }

    // epilogue: direct fp32 stores
#pragma unroll
    for (int mt = 0; mt < 2; mt++) {
#pragma unroll
        for (int nt = 0; nt < 8; nt++) {
            int row = m0 + wm * 32 + mt * 16 + (lane >> 2);
            int col = n0 + wn * 64 + nt * 8 + (lane & 3) * 2;
            float2 v0 = make_float2(acc[mt][nt][0], acc[mt][nt][1]);
            float2 v1 = make_float2(acc[mt][nt][2], acc[mt][nt][3]);
            *reinterpret_cast<float2*>(out + (size_t)row * N_DIM + col) = v0;
            *reinterpret_cast<float2*>(out + (size_t)(row + 8) * N_DIM + col) = v1;
        }
    }
}

// ---------------------------------------------------------------------------
// kernel_launch
// ---------------------------------------------------------------------------
extern "C" void kernel_launch(void* const* d_in, const int* in_sizes, int n_in,
                              void* d_out, int out_size) {
    const float* x = (const float*)d_in[0];
    const int* gi = (const int*)d_in[1];
    const float* scale = (const float*)d_in[2];
    float* out = (float*)d_out;

    prep_kernel<<<W_BLOCKS + X_BLOCKS, 256>>>(x, gi, scale);

    cudaFuncSetAttribute(gemm_kernel, cudaFuncAttributeMaxDynamicSharedMemorySize, SMEM_BYTES);
    dim3 grid(N_DIM / BN, M_DIM / BM);  // (64, 32)
    gemm_kernel<<<grid, 256, SMEM_BYTES>>>(out);
}